// round 8
// baseline (speedup 1.0000x reference)
#include <cuda_runtime.h>
#include <cuda_bf16.h>
#include <math.h>
#include <stdint.h>

#define B_   4096
#define T_   32
#define H_   512
#define NG   2048   // 4*H
#define EMB_ 64
#define V_   256
#define O_   64

// quantization scales (compile-time)
#define S1H_ (1.0f / 127.0f)
#define S2H_ (1.0f / 16256.0f)           // S1H/128
#define S1W_ (0.0441941738f / 127.0f)    // 1/sqrt(512)/127
#define S2W_ (S1W_ / 128.0f)

// ---------------- persistent scratch ----------------
__device__ float d_table[2][V_][NG];                 // per-char gate preactivation (+biases), mma-column layout
__device__ signed char d_w1[2][NG][H_];              // Whh int8 level-1, rows = mma columns, K contiguous
__device__ signed char d_w2[2][NG][H_];              // level-2
__device__ signed char d_h1[2][2][B_ * H_];          // [dir][pp] h int8 level-1
__device__ signed char d_h2[2][2][B_ * H_];          // level-2
__device__ float d_c[2][B_ * H_];                    // cell state, thread-private coalesced layout

// column n (0..2047) -> torch gate row j
__device__ __forceinline__ int jmap2(int n) {
    int gate = (((n >> 3) & 1) << 1) | (n & 1);
    int u    = ((n >> 4) << 2) | ((n >> 1) & 3);
    return gate * H_ + u;
}
__device__ __forceinline__ float sig_f(float x) {
    return __fdividef(1.0f, 1.0f + __expf(-x));
}
__device__ __forceinline__ float tanh_f(float x) {
    return __fdividef(2.0f, 1.0f + __expf(-2.0f * x)) - 1.0f;
}

// ---------------- PTX helpers (plain-target safe) ----------------
__device__ __forceinline__ uint32_t smem_u32(const void* p) {
    uint32_t a;
    asm("{ .reg .u64 t; cvta.to.shared.u64 t, %1; cvt.u32.u64 %0, t; }" : "=r"(a) : "l"(p));
    return a;
}
__device__ __forceinline__ void cp16(uint32_t saddr, const void* g) {
    asm volatile("cp.async.cg.shared.global [%0], [%1], 16;" :: "r"(saddr), "l"(g));
}
#define CP_COMMIT() asm volatile("cp.async.commit_group;" ::: "memory")
#define CP_WAIT(n)  asm volatile("cp.async.wait_group %0;" :: "n"(n) : "memory")

__device__ __forceinline__ void ldsm_x4(uint32_t addr, uint32_t* r) {
    asm volatile("ldmatrix.sync.aligned.m8n8.x4.shared.b16 {%0,%1,%2,%3}, [%4];"
        : "=r"(r[0]), "=r"(r[1]), "=r"(r[2]), "=r"(r[3]) : "r"(addr));
}
__device__ __forceinline__ void mma_s8(int* c, const uint32_t* a, uint32_t b0, uint32_t b1) {
    asm volatile("mma.sync.aligned.m16n8k32.row.col.s32.s8.s8.s32 "
        "{%0,%1,%2,%3}, {%4,%5,%6,%7}, {%8,%9}, {%0,%1,%2,%3};"
        : "+r"(c[0]), "+r"(c[1]), "+r"(c[2]), "+r"(c[3])
        : "r"(a[0]), "r"(a[1]), "r"(a[2]), "r"(a[3]), "r"(b0), "r"(b1));
}

// 64B-row layout, conflict-free swizzle: 16B chunk index ^= (row>>1)&3
__device__ __forceinline__ uint32_t swzoff(int row, int cb) {
    uint32_t chunk = ((uint32_t)cb >> 4) ^ (((uint32_t)row >> 1) & 3u);
    return (uint32_t)row * 64 + chunk * 16;
}

// ---------------- SMEM layout: CTA 128(M)x64(N), K-tile 64 (int8 -> 64B rows), 4 stages ----------------
#define TILE_A  8192    // 128 rows x 64B
#define TILE_B  4096    // 64 rows x 64B
#define STG_SZ  24576   // A1,A2,B1,B2
#define NSTG    4
#define OFF_A1(s) ((s) * STG_SZ + 0)
#define OFF_A2(s) ((s) * STG_SZ + TILE_A)
#define OFF_B1(s) ((s) * STG_SZ + 2 * TILE_A)
#define OFF_B2(s) ((s) * STG_SZ + 2 * TILE_A + TILE_B)
#define SMEM_TOTAL (NSTG * STG_SZ)   // 98304

// ---------------- one-off precompute ----------------
__global__ void build_table(const float* __restrict__ emb,
                            const float* __restrict__ Wih1, const float* __restrict__ bih1, const float* __restrict__ bhh1,
                            const float* __restrict__ Wih2, const float* __restrict__ bih2, const float* __restrict__ bhh2) {
    int n   = blockIdx.x * 128 + threadIdx.x;
    int v   = blockIdx.y;
    int dir = blockIdx.z;
    const float* Wih = dir ? Wih2 : Wih1;
    const float* bi  = dir ? bih2 : bih1;
    const float* bh  = dir ? bhh2 : bhh1;
    int j = jmap2(n);
    float s = bi[j] + bh[j];
    const float* e = emb + v * EMB_;
    const float* w = Wih + j * EMB_;
#pragma unroll 16
    for (int k = 0; k < EMB_; k++) s += e[k] * w[k];
    d_table[dir][v][n] = s;
}

__global__ void build_w8(const float* __restrict__ Whh1, const float* __restrict__ Whh2) {
    int k   = blockIdx.x * 128 + threadIdx.x;
    int n   = blockIdx.y;
    int dir = blockIdx.z;
    const float* W = dir ? Whh2 : Whh1;
    float w = W[jmap2(n) * H_ + k];
    int q1 = __float2int_rn(w / S1W_);
    q1 = max(-127, min(127, q1));
    float r = w - (float)q1 * S1W_;
    int q2 = __float2int_rn(r / S2W_);
    q2 = max(-127, min(127, q2));
    d_w1[dir][n][k] = (signed char)q1;
    d_w2[dir][n][k] = (signed char)q2;
}

__global__ void init_state() {
    int i = blockIdx.x * 256 + threadIdx.x;
    if (i < B_ * H_) {
        d_h1[0][0][i] = 0; d_h1[1][0][i] = 0;
        d_h2[0][0][i] = 0; d_h2[1][0][i] = 0;
        d_c[0][i] = 0.f;   d_c[1][i] = 0.f;
    }
}

// ---------------- async stage: one ROWSx64 int8 tile (256 threads) ----------------
template<int ROWS>
__device__ __forceinline__ void stage_tile(uint32_t sdst,
                                           const signed char* __restrict__ src,
                                           int rowbase, int k0, int tid) {
    constexpr int ITERS = (ROWS * 4) / 256;
#pragma unroll
    for (int j = 0; j < ITERS; j++) {
        int lin = tid + j * 256;
        int row = lin >> 2;
        int c   = lin & 3;
        uint32_t chunk = (uint32_t)c ^ (((uint32_t)row >> 1) & 3u);
        cp16(sdst + (uint32_t)row * 64 + chunk * 16,
             src + (size_t)(rowbase + row) * H_ + k0 + c * 16);
    }
}

// ---------------- fused recurrent step: 2-level int8 mma ----------------
// CTA 128(M) x 64(N gate-cols), 256 threads = 8 warps (4 row-bands x 2 col-bands), warp tile 32x32
__global__ void __launch_bounds__(256, 2) lstm_step_mma(const int* __restrict__ x, int t, int pp) {
    extern __shared__ __align__(1024) char sm[];
    const int dir  = blockIdx.z;
    const int tcol = dir ? (T_ - 1 - t) : t;
    const int n0   = blockIdx.x * 64;
    const int b0   = blockIdx.y * 128;

    const signed char* __restrict__ h1 = d_h1[dir][pp];
    const signed char* __restrict__ h2 = d_h2[dir][pp];
    signed char* __restrict__ h1_n = d_h1[dir][pp ^ 1];
    signed char* __restrict__ h2_n = d_h2[dir][pp ^ 1];
    float* __restrict__ cst = d_c[dir];
    const signed char* __restrict__ W1 = &d_w1[dir][0][0];
    const signed char* __restrict__ W2 = &d_w2[dir][0][0];

    const uint32_t sb = smem_u32(sm);
    const int tid  = threadIdx.x;
    const int wid  = tid >> 5;
    const int lane = tid & 31;
    const int wm   = wid >> 1;    // 0..3: 32-row band
    const int wn   = wid & 1;     // 0..1: 32-col band
    const int g    = lane >> 2;
    const int tg   = lane & 3;
    const int lrow  = lane & 15;
    const int lhalf = lane >> 4;

    // prefetch chars for the epilogue
    int chv[2][2];
#pragma unroll
    for (int i = 0; i < 2; i++) {
        const int r0 = wm * 32 + i * 16 + g;
        chv[i][0] = x[(size_t)(b0 + r0) * T_ + tcol];
        chv[i][1] = x[(size_t)(b0 + r0 + 8) * T_ + tcol];
    }

    // per-thread ldsm offsets (loop-invariant); kk in {0,1} selects 32B half of 64B row
    uint32_t oA[2][2], oB[2][2];
#pragma unroll
    for (int kk = 0; kk < 2; kk++) {
        const int kb = kk * 32 + lhalf * 16;
#pragma unroll
        for (int i = 0; i < 2; i++) oA[i][kk] = swzoff(wm * 32 + i * 16 + lrow, kb);
#pragma unroll
        for (int q = 0; q < 2; q++) oB[q][kk] = swzoff(wn * 32 + q * 16 + lrow, kb);
    }

    int acc1[2][4][4], acc2[2][4][4];
#pragma unroll
    for (int i = 0; i < 2; i++)
#pragma unroll
        for (int j = 0; j < 4; j++)
#pragma unroll
            for (int r = 0; r < 4; r++) { acc1[i][j][r] = 0; acc2[i][j][r] = 0; }

    // prologue: stage k-tiles 0,1,2
#pragma unroll
    for (int s = 0; s < 3; s++) {
        stage_tile<128>(sb + OFF_A1(s), h1, b0, s * 64, tid);
        stage_tile<128>(sb + OFF_A2(s), h2, b0, s * 64, tid);
        stage_tile<64>(sb + OFF_B1(s), W1, n0, s * 64, tid);
        stage_tile<64>(sb + OFF_B2(s), W2, n0, s * 64, tid);
        CP_COMMIT();
    }

#pragma unroll
    for (int kt = 0; kt < 8; kt++) {
        if (kt < 6) { CP_WAIT(2); } else if (kt == 6) { CP_WAIT(1); } else { CP_WAIT(0); }
        __syncthreads();
        if (kt + 3 < 8) {
            const int nb = (kt + 3) % NSTG;
            const int k0 = (kt + 3) * 64;
            stage_tile<128>(sb + OFF_A1(nb), h1, b0, k0, tid);
            stage_tile<128>(sb + OFF_A2(nb), h2, b0, k0, tid);
            stage_tile<64>(sb + OFF_B1(nb), W1, n0, k0, tid);
            stage_tile<64>(sb + OFF_B2(nb), W2, n0, k0, tid);
            CP_COMMIT();
        }
        const int buf = kt % NSTG;
        const uint32_t baseA1 = sb + OFF_A1(buf), baseA2 = sb + OFF_A2(buf);
        const uint32_t baseB1 = sb + OFF_B1(buf), baseB2 = sb + OFF_B2(buf);
#pragma unroll
        for (int kk = 0; kk < 2; kk++) {
            uint32_t a1[2][4], b1f[2][4], b2f[2][4];
            // P1: q1(A) x q1(B) -> acc1
#pragma unroll
            for (int i = 0; i < 2; i++) ldsm_x4(baseA1 + oA[i][kk], a1[i]);
#pragma unroll
            for (int q = 0; q < 2; q++) ldsm_x4(baseB1 + oB[q][kk], b1f[q]);
#pragma unroll
            for (int i = 0; i < 2; i++)
#pragma unroll
                for (int q = 0; q < 2; q++)
#pragma unroll
                    for (int nb2 = 0; nb2 < 2; nb2++)
                        mma_s8(acc1[i][q * 2 + nb2], a1[i], b1f[q][nb2], b1f[q][nb2 + 2]);
            // P2: q1(A) x q2(B) -> acc2
#pragma unroll
            for (int q = 0; q < 2; q++) ldsm_x4(baseB2 + oB[q][kk], b2f[q]);
#pragma unroll
            for (int i = 0; i < 2; i++)
#pragma unroll
                for (int q = 0; q < 2; q++)
#pragma unroll
                    for (int nb2 = 0; nb2 < 2; nb2++)
                        mma_s8(acc2[i][q * 2 + nb2], a1[i], b2f[q][nb2], b2f[q][nb2 + 2]);
            // P3: q2(A) x q1(B) -> acc2 (reuse b1f)
#pragma unroll
            for (int i = 0; i < 2; i++) ldsm_x4(baseA2 + oA[i][kk], a1[i]);
#pragma unroll
            for (int i = 0; i < 2; i++)
#pragma unroll
                for (int q = 0; q < 2; q++)
#pragma unroll
                    for (int nb2 = 0; nb2 < 2; nb2++)
                        mma_s8(acc2[i][q * 2 + nb2], a1[i], b1f[q][nb2], b1f[q][nb2 + 2]);
        }
    }

    __syncthreads();   // smem reads retired before epilogue staging reuse

    // ---------------- epilogue ----------------
    const float SC1 = S1W_ * S1H_;
    const float SC2 = SC1 * (1.0f / 128.0f);
    const int cbase = (((blockIdx.y * 32 + blockIdx.x) * 256 + tid) << 3);
    float cv[8];
#pragma unroll
    for (int q = 0; q < 2; q++) *(float4*)&cv[q * 4] = *(const float4*)&cst[cbase + q * 4];

#pragma unroll
    for (int i = 0; i < 2; i++) {
        const int r0 = wm * 32 + i * 16 + g;
        const float* trow0 = &d_table[dir][chv[i][0]][n0];
        const float* trow1 = &d_table[dir][chv[i][1]][n0];
#pragma unroll
        for (int jj = 0; jj < 2; jj++) {
            const int colIF = wn * 32 + jj * 16 + 2 * tg;   // (i,f) cols; (g,o) at +8
            const int u_l   = (wn * 2 + jj) * 4 + tg;        // local unit 0..15
#pragma unroll
            for (int half = 0; half < 2; half++) {
                const float* trow = half ? trow1 : trow0;
                const float2 tif = *(const float2*)&trow[colIF];
                const float2 tgo = *(const float2*)&trow[colIF + 8];
                float gi = fmaf(SC1, (float)acc1[i][jj * 2 + 0][half * 2 + 0],
                          fmaf(SC2, (float)acc2[i][jj * 2 + 0][half * 2 + 0], tif.x));
                float gf = fmaf(SC1, (float)acc1[i][jj * 2 + 0][half * 2 + 1],
                          fmaf(SC2, (float)acc2[i][jj * 2 + 0][half * 2 + 1], tif.y));
                float gg = fmaf(SC1, (float)acc1[i][jj * 2 + 1][half * 2 + 0],
                          fmaf(SC2, (float)acc2[i][jj * 2 + 1][half * 2 + 0], tgo.x));
                float go = fmaf(SC1, (float)acc1[i][jj * 2 + 1][half * 2 + 1],
                          fmaf(SC2, (float)acc2[i][jj * 2 + 1][half * 2 + 1], tgo.y));
                const int idx = i * 4 + jj * 2 + half;
                float c_new = sig_f(gf) * cv[idx] + sig_f(gi) * tanh_f(gg);
                cv[idx] = c_new;
                const float hv = sig_f(go) * tanh_f(c_new);
                int q1 = __float2int_rn(hv * 127.0f);
                float rres = fmaf((float)q1, -S1H_, hv);
                int q2 = __float2int_rn(rres * 16256.0f);
                const int rl = r0 + half * 8;   // local row 0..127
                *(signed char*)(sm + rl * 16 + u_l) = (signed char)q1;
                *(signed char*)(sm + 4096 + rl * 16 + u_l) = (signed char)q2;
            }
        }
    }
#pragma unroll
    for (int q = 0; q < 2; q++) *(float4*)&cst[cbase + q * 4] = *(const float4*)&cv[q * 4];

    __syncthreads();
    // coalesced h store: 128 rows x 16 units (16B/row) per level
    const int u0 = blockIdx.x * 16;   // CTA's unit base
    {
        const int row = tid & 127;
        const int lvl = tid >> 7;
        uint4 v = *(const uint4*)(sm + lvl * 4096 + row * 16);
        signed char* dst = lvl ? h2_n : h1_n;
        *(uint4*)(dst + (size_t)(b0 + row) * H_ + u0) = v;
    }
}

// ---------------- classifier head + softmax ----------------
__global__ void head_kernel(const float* __restrict__ Wlin, const float* __restrict__ blin,
                            float* __restrict__ out) {
    const int b    = blockIdx.x;
    const int tid  = threadIdx.x;
    const int w    = tid >> 5;
    const int lane = tid & 31;

    __shared__ __align__(16) float hrow[1024];
    __shared__ float lg[O_];
    __shared__ float red[2];

    for (int i = tid; i < H_; i += 256) {
        hrow[i]      = ((float)d_h1[0][0][b * H_ + i] * 128.0f + (float)d_h2[0][0][b * H_ + i]) * (1.0f / 16256.0f);
        hrow[H_ + i] = ((float)d_h1[1][0][b * H_ + i] * 128.0f + (float)d_h2[1][0][b * H_ + i]) * (1.0f / 16256.0f);
    }
    __syncthreads();

    const float4* hr4 = (const float4*)hrow;
#pragma unroll
    for (int oo = 0; oo < 8; oo++) {
        const int o = w * 8 + oo;
        const float4* wl = (const float4*)(Wlin + o * 1024);
        float s = 0.f;
#pragma unroll
        for (int it = 0; it < 8; it++) {
            float4 a  = hr4[it * 32 + lane];
            float4 bw = wl[it * 32 + lane];
            s += a.x * bw.x + a.y * bw.y + a.z * bw.z + a.w * bw.w;
        }
#pragma unroll
        for (int off = 16; off; off >>= 1) s += __shfl_down_sync(0xffffffffu, s, off);
        if (lane == 0) lg[o] = s + blin[o];
    }
    __syncthreads();

    if (tid == 0) {
        float m = lg[0];
        for (int i = 1; i < O_; i++) m = fmaxf(m, lg[i]);
        red[0] = m;
    }
    __syncthreads();
    if (tid < O_) lg[tid] = expf(lg[tid] - red[0]);
    __syncthreads();
    if (tid == 0) {
        float s = 0.f;
        for (int i = 0; i < O_; i++) s += lg[i];
        red[1] = 1.0f / s;
    }
    __syncthreads();
    if (tid < O_) out[b * O_ + tid] = lg[tid] * red[1];
}

// ---------------- launch ----------------
extern "C" void kernel_launch(void* const* d_in, const int* in_sizes, int n_in,
                              void* d_out, int out_size) {
    const int*   x    = (const int*)d_in[0];
    const float* emb  = (const float*)d_in[2];
    const float* Wih1 = (const float*)d_in[3];
    const float* Whh1 = (const float*)d_in[4];
    const float* bih1 = (const float*)d_in[5];
    const float* bhh1 = (const float*)d_in[6];
    const float* Wih2 = (const float*)d_in[7];
    const float* Whh2 = (const float*)d_in[8];
    const float* bih2 = (const float*)d_in[9];
    const float* bhh2 = (const float*)d_in[10];
    const float* Wlin = (const float*)d_in[11];
    const float* blin = (const float*)d_in[12];
    float* out = (float*)d_out;

    cudaFuncSetAttribute(lstm_step_mma, cudaFuncAttributeMaxDynamicSharedMemorySize, SMEM_TOTAL);

    dim3 g1(NG / 128, V_, 2);
    build_table<<<g1, 128>>>(emb, Wih1, bih1, bhh1, Wih2, bih2, bhh2);
    dim3 g2(H_ / 128, NG, 2);
    build_w8<<<g2, 128>>>(Whh1, Whh2);
    init_state<<<(B_ * H_ + 255) / 256, 256>>>();

    dim3 gs(NG / 64, B_ / 128, 2);   // (32, 32, 2) = 2048 CTAs, 2/SM
    for (int t = 0; t < T_; t++) {
        lstm_step_mma<<<gs, 256, SMEM_TOTAL>>>(x, t, t & 1);
    }
    head_kernel<<<B_, 256>>>(Wlin, blin, out);
}

// round 9
// speedup vs baseline: 3.6055x; 3.6055x over previous
#include <cuda_runtime.h>
#include <cuda_fp16.h>
#include <math.h>
#include <stdint.h>

#define B_   4096
#define T_   32
#define H_   512
#define NG   2048   // 4*H
#define EMB_ 64
#define V_   256
#define O_   64

#define WSCALE 16.0f
#define INV_WSCALE 0.0625f

// ---------------- persistent scratch ----------------
__device__ float d_table[2][V_][NG];            // per-char gate preactivation (+biases), mma-column layout
__device__ __half d_wh[2][NG][H_];              // (W*16) fp16 hi, rows = mma columns, K contiguous
__device__ __half d_wl[2][NG][H_];              // (W*16) fp16 lo
__device__ __half d_hx[2][2][B_ * H_];          // [dir][pp] h (fp16-rounded, exact operand)
__device__ float d_c[2][B_ * H_];               // cell state, thread-private coalesced layout

// column n (0..2047) -> torch gate row j
__device__ __forceinline__ int jmap2(int n) {
    int gate = (((n >> 3) & 1) << 1) | (n & 1);
    int u    = ((n >> 4) << 2) | ((n >> 1) & 3);
    return gate * H_ + u;
}
__device__ __forceinline__ float sig_f(float x) {
    return __fdividef(1.0f, 1.0f + __expf(-x));
}
__device__ __forceinline__ float tanh_f(float x) {
    return __fdividef(2.0f, 1.0f + __expf(-2.0f * x)) - 1.0f;
}

// ---------------- PTX helpers (plain-target safe) ----------------
__device__ __forceinline__ uint32_t smem_u32(const void* p) {
    uint32_t a;
    asm("{ .reg .u64 t; cvta.to.shared.u64 t, %1; cvt.u32.u64 %0, t; }" : "=r"(a) : "l"(p));
    return a;
}
__device__ __forceinline__ void cp16(uint32_t saddr, const void* g) {
    asm volatile("cp.async.cg.shared.global [%0], [%1], 16;" :: "r"(saddr), "l"(g));
}
#define CP_COMMIT() asm volatile("cp.async.commit_group;" ::: "memory")
#define CP_WAIT(n)  asm volatile("cp.async.wait_group %0;" :: "n"(n) : "memory")

__device__ __forceinline__ void ldsm_x4(uint32_t addr, uint32_t* r) {
    asm volatile("ldmatrix.sync.aligned.m8n8.x4.shared.b16 {%0,%1,%2,%3}, [%4];"
        : "=r"(r[0]), "=r"(r[1]), "=r"(r[2]), "=r"(r[3]) : "r"(addr));
}
__device__ __forceinline__ void mma_f16(float* c, const uint32_t* a, uint32_t b0, uint32_t b1) {
    asm volatile("mma.sync.aligned.m16n8k16.row.col.f32.f16.f16.f32 "
        "{%0,%1,%2,%3}, {%4,%5,%6,%7}, {%8,%9}, {%0,%1,%2,%3};"
        : "+f"(c[0]), "+f"(c[1]), "+f"(c[2]), "+f"(c[3])
        : "r"(a[0]), "r"(a[1]), "r"(a[2]), "r"(a[3]), "r"(b0), "r"(b1));
}

// 64B-row layout, conflict-free swizzle: 16B chunk index ^= (row>>1)&3
__device__ __forceinline__ uint32_t swzoff(int row, int cb) {
    uint32_t chunk = ((uint32_t)cb >> 4) ^ (((uint32_t)row >> 1) & 3u);
    return (uint32_t)row * 64 + chunk * 16;
}

// ---------------- SMEM layout: CTA 128x128, K-tile 32, 4 stages ----------------
// per tile: 128 rows x 64B = 8192; per stage A, Bh, Bl = 24576
#define TILE_SZ  8192
#define STG_SZ   24576
#define NSTG     4
#define OFF_A(s)  ((s) * STG_SZ + 0)
#define OFF_BH(s) ((s) * STG_SZ + TILE_SZ)
#define OFF_BL(s) ((s) * STG_SZ + 2 * TILE_SZ)
#define SMEM_TOTAL (NSTG * STG_SZ)   // 98304
#define HSTG 80                      // h-staging row stride (bytes)

// ---------------- one-off precompute ----------------
__global__ void build_table(const float* __restrict__ emb,
                            const float* __restrict__ Wih1, const float* __restrict__ bih1, const float* __restrict__ bhh1,
                            const float* __restrict__ Wih2, const float* __restrict__ bih2, const float* __restrict__ bhh2) {
    int n   = blockIdx.x * 128 + threadIdx.x;
    int v   = blockIdx.y;
    int dir = blockIdx.z;
    const float* Wih = dir ? Wih2 : Wih1;
    const float* bi  = dir ? bih2 : bih1;
    const float* bh  = dir ? bhh2 : bhh1;
    int j = jmap2(n);
    float s = bi[j] + bh[j];
    const float* e = emb + v * EMB_;
    const float* w = Wih + j * EMB_;
#pragma unroll 16
    for (int k = 0; k < EMB_; k++) s += e[k] * w[k];
    d_table[dir][v][n] = s;
}

__global__ void build_wt(const float* __restrict__ Whh1, const float* __restrict__ Whh2) {
    int k   = blockIdx.x * 128 + threadIdx.x;
    int n   = blockIdx.y;
    int dir = blockIdx.z;
    const float* W = dir ? Whh2 : Whh1;
    float w = W[jmap2(n) * H_ + k] * WSCALE;
    __half wh = __float2half_rn(w);
    d_wh[dir][n][k] = wh;
    d_wl[dir][n][k] = __float2half_rn(w - __half2float(wh));
}

__global__ void init_state() {
    int i = blockIdx.x * 256 + threadIdx.x;
    if (i < B_ * H_) {
        __half z = __float2half_rn(0.f);
        d_hx[0][0][i] = z; d_hx[1][0][i] = z;
        d_c[0][i] = 0.f;   d_c[1][i] = 0.f;
    }
}

// ---------------- async stage: one 128x32 fp16 tile (256 threads) ----------------
__device__ __forceinline__ void stage_tile(uint32_t sdst,
                                           const __half* __restrict__ src,
                                           int rowbase, int k0, int tid) {
#pragma unroll
    for (int j = 0; j < 2; j++) {
        int lin = tid + j * 256;
        int row = lin >> 2;
        int c   = lin & 3;
        uint32_t chunk = (uint32_t)c ^ (((uint32_t)row >> 1) & 3u);
        cp16(sdst + (uint32_t)row * 64 + chunk * 16,
             (const char*)(src + (size_t)(rowbase + row) * H_ + k0) + c * 16);
    }
}

// ---------------- fused recurrent step: 2-product fp16 mma ----------------
__global__ void __launch_bounds__(256, 2) lstm_step_mma(const int* __restrict__ x, int t, int pp) {
    extern __shared__ __align__(1024) char sm[];
    const int dir  = blockIdx.z;
    const int tcol = dir ? (T_ - 1 - t) : t;
    const int n0   = blockIdx.x * 128;
    const int b0   = blockIdx.y * 128;

    const __half* __restrict__ hx = d_hx[dir][pp];
    __half* __restrict__ hx_n = d_hx[dir][pp ^ 1];
    float* __restrict__ cst = d_c[dir];
    const __half* __restrict__ Wh = &d_wh[dir][0][0];
    const __half* __restrict__ Wl = &d_wl[dir][0][0];

    const uint32_t sb = smem_u32(sm);
    const int tid  = threadIdx.x;
    const int wid  = tid >> 5;
    const int lane = tid & 31;
    const int wm   = wid >> 1;    // 0..3: 32-row band
    const int wn   = wid & 1;     // 0..1: 64-col band
    const int g    = lane >> 2;
    const int tg   = lane & 3;
    const int lrow  = lane & 15;
    const int lhalf = lane >> 4;

    // prefetch chars for the epilogue
    int chv[2][2];
#pragma unroll
    for (int i = 0; i < 2; i++) {
        const int r0 = wm * 32 + i * 16 + g;
        chv[i][0] = x[(size_t)(b0 + r0) * T_ + tcol];
        chv[i][1] = x[(size_t)(b0 + r0 + 8) * T_ + tcol];
    }

    // per-thread ldsm offsets (loop-invariant)
    uint32_t oA[2][2], oB[4][2];
#pragma unroll
    for (int kk = 0; kk < 2; kk++) {
        const int kb = kk * 32 + lhalf * 16;
#pragma unroll
        for (int i = 0; i < 2; i++) oA[i][kk] = swzoff(wm * 32 + i * 16 + lrow, kb);
#pragma unroll
        for (int q = 0; q < 4; q++) oB[q][kk] = swzoff(wn * 64 + q * 16 + lrow, kb);
    }

    float acc[2][8][4];
#pragma unroll
    for (int i = 0; i < 2; i++)
#pragma unroll
        for (int j = 0; j < 8; j++)
#pragma unroll
            for (int r = 0; r < 4; r++) acc[i][j][r] = 0.f;

    // prologue: stage k-tiles 0,1,2
#pragma unroll
    for (int s = 0; s < 3; s++) {
        stage_tile(sb + OFF_A(s),  hx, b0, s * 32, tid);
        stage_tile(sb + OFF_BH(s), Wh, n0, s * 32, tid);
        stage_tile(sb + OFF_BL(s), Wl, n0, s * 32, tid);
        CP_COMMIT();
    }

#pragma unroll
    for (int kt = 0; kt < 16; kt++) {
        if (kt < 14) { CP_WAIT(2); } else if (kt == 14) { CP_WAIT(1); } else { CP_WAIT(0); }
        __syncthreads();
        if (kt + 3 < 16) {
            const int nb = (kt + 3) % NSTG;
            const int k0 = (kt + 3) * 32;
            stage_tile(sb + OFF_A(nb),  hx, b0, k0, tid);
            stage_tile(sb + OFF_BH(nb), Wh, n0, k0, tid);
            stage_tile(sb + OFF_BL(nb), Wl, n0, k0, tid);
            CP_COMMIT();
        }
        const int buf = kt % NSTG;
        const uint32_t baseA  = sb + OFF_A(buf);
        const uint32_t baseBH = sb + OFF_BH(buf), baseBL = sb + OFF_BL(buf);
#pragma unroll
        for (int kk = 0; kk < 2; kk++) {
            uint32_t af[2][4], bf4[4][4];
            // ---- product 1: A x Wh ----
#pragma unroll
            for (int i = 0; i < 2; i++) ldsm_x4(baseA + oA[i][kk], af[i]);
#pragma unroll
            for (int q = 0; q < 4; q++) ldsm_x4(baseBH + oB[q][kk], bf4[q]);
#pragma unroll
            for (int i = 0; i < 2; i++)
#pragma unroll
                for (int q = 0; q < 4; q++)
#pragma unroll
                    for (int nb2 = 0; nb2 < 2; nb2++)
                        mma_f16(acc[i][q * 2 + nb2], af[i], bf4[q][nb2], bf4[q][nb2 + 2]);
            // ---- product 2: A x Wl (reuse A frags) ----
#pragma unroll
            for (int q = 0; q < 4; q++) ldsm_x4(baseBL + oB[q][kk], bf4[q]);
#pragma unroll
            for (int i = 0; i < 2; i++)
#pragma unroll
                for (int q = 0; q < 4; q++)
#pragma unroll
                    for (int nb2 = 0; nb2 < 2; nb2++)
                        mma_f16(acc[i][q * 2 + nb2], af[i], bf4[q][nb2], bf4[q][nb2 + 2]);
        }
    }

    __syncthreads();   // all mma smem reads retired before epilogue staging reuse

    // ---------------- epilogue: gates + cell update, in-register ----------------
    const int cbase = (((blockIdx.y * 16 + blockIdx.x) * 256 + tid) << 4);
    float cv[16];
#pragma unroll
    for (int q = 0; q < 4; q++) *(float4*)&cv[q * 4] = *(const float4*)&cst[cbase + q * 4];

#pragma unroll
    for (int i = 0; i < 2; i++) {
        const int r0 = wm * 32 + i * 16 + g;
        const float* trow0 = &d_table[dir][chv[i][0]][n0];
        const float* trow1 = &d_table[dir][chv[i][1]][n0];
#pragma unroll
        for (int jj = 0; jj < 4; jj++) {
            const int colIF = wn * 64 + jj * 16 + 2 * tg;
            const int u_l   = (wn * 4 + jj) * 4 + tg;
#pragma unroll
            for (int half = 0; half < 2; half++) {
                const float* trow = half ? trow1 : trow0;
                const float2 tif = *(const float2*)&trow[colIF];
                const float2 tgo = *(const float2*)&trow[colIF + 8];
                float gi = fmaf(INV_WSCALE, acc[i][jj * 2 + 0][half * 2 + 0], tif.x);
                float gf = fmaf(INV_WSCALE, acc[i][jj * 2 + 0][half * 2 + 1], tif.y);
                float gg = fmaf(INV_WSCALE, acc[i][jj * 2 + 1][half * 2 + 0], tgo.x);
                float go = fmaf(INV_WSCALE, acc[i][jj * 2 + 1][half * 2 + 1], tgo.y);
                const int idx = i * 8 + jj * 2 + half;
                float c_new = sig_f(gf) * cv[idx] + sig_f(gi) * tanh_f(gg);
                cv[idx] = c_new;
                const float hv = sig_f(go) * tanh_f(c_new);
                const int rl = r0 + half * 8;
                *(__half*)(sm + rl * HSTG + u_l * 2) = __float2half_rn(hv);
            }
        }
    }
#pragma unroll
    for (int q = 0; q < 4; q++) *(float4*)&cst[cbase + q * 4] = *(const float4*)&cv[q * 4];

    __syncthreads();
    // coalesced h store: 128 rows x 32 units (64B/row)
    const int u0 = n0 >> 2;
    {
        const int row = tid >> 1;
        const int q   = tid & 1;
        uint4 v0 = *(const uint4*)(sm + row * HSTG + q * 32);
        uint4 v1 = *(const uint4*)(sm + row * HSTG + q * 32 + 16);
        char* dst = (char*)(hx_n + (size_t)(b0 + row) * H_ + u0) + q * 32;
        *(uint4*)dst = v0;
        *(uint4*)(dst + 16) = v1;
    }
}

// ---------------- classifier head + softmax ----------------
__global__ void head_kernel(const float* __restrict__ Wlin, const float* __restrict__ blin,
                            float* __restrict__ out) {
    const int b    = blockIdx.x;
    const int tid  = threadIdx.x;
    const int w    = tid >> 5;
    const int lane = tid & 31;

    __shared__ __align__(16) float hrow[1024];
    __shared__ float lg[O_];
    __shared__ float red[2];

    for (int i = tid; i < H_; i += 256) {
        hrow[i]      = __half2float(d_hx[0][0][b * H_ + i]);
        hrow[H_ + i] = __half2float(d_hx[1][0][b * H_ + i]);
    }
    __syncthreads();

    const float4* hr4 = (const float4*)hrow;
#pragma unroll
    for (int oo = 0; oo < 8; oo++) {
        const int o = w * 8 + oo;
        const float4* wl = (const float4*)(Wlin + o * 1024);
        float s = 0.f;
#pragma unroll
        for (int it = 0; it < 8; it++) {
            float4 a  = hr4[it * 32 + lane];
            float4 bw = wl[it * 32 + lane];
            s += a.x * bw.x + a.y * bw.y + a.z * bw.z + a.w * bw.w;
        }
#pragma unroll
        for (int off = 16; off; off >>= 1) s += __shfl_down_sync(0xffffffffu, s, off);
        if (lane == 0) lg[o] = s + blin[o];
    }
    __syncthreads();

    if (tid == 0) {
        float m = lg[0];
        for (int i = 1; i < O_; i++) m = fmaxf(m, lg[i]);
        red[0] = m;
    }
    __syncthreads();
    if (tid < O_) lg[tid] = expf(lg[tid] - red[0]);
    __syncthreads();
    if (tid == 0) {
        float s = 0.f;
        for (int i = 0; i < O_; i++) s += lg[i];
        red[1] = 1.0f / s;
    }
    __syncthreads();
    if (tid < O_) out[b * O_ + tid] = lg[tid] * red[1];
}

// ---------------- launch ----------------
extern "C" void kernel_launch(void* const* d_in, const int* in_sizes, int n_in,
                              void* d_out, int out_size) {
    const int*   x    = (const int*)d_in[0];
    const float* emb  = (const float*)d_in[2];
    const float* Wih1 = (const float*)d_in[3];
    const float* Whh1 = (const float*)d_in[4];
    const float* bih1 = (const float*)d_in[5];
    const float* bhh1 = (const float*)d_in[6];
    const float* Wih2 = (const float*)d_in[7];
    const float* Whh2 = (const float*)d_in[8];
    const float* bih2 = (const float*)d_in[9];
    const float* bhh2 = (const float*)d_in[10];
    const float* Wlin = (const float*)d_in[11];
    const float* blin = (const float*)d_in[12];
    float* out = (float*)d_out;

    cudaFuncSetAttribute(lstm_step_mma, cudaFuncAttributeMaxDynamicSharedMemorySize, SMEM_TOTAL);

    dim3 g1(NG / 128, V_, 2);
    build_table<<<g1, 128>>>(emb, Wih1, bih1, bhh1, Wih2, bih2, bhh2);
    dim3 g2(H_ / 128, NG, 2);
    build_wt<<<g2, 128>>>(Whh1, Whh2);
    init_state<<<(B_ * H_ + 255) / 256, 256>>>();

    dim3 gs(NG / 128, B_ / 128, 2);   // (16, 32, 2) = 1024 CTAs, 2/SM
    for (int t = 0; t < T_; t++) {
        lstm_step_mma<<<gs, 256, SMEM_TOTAL>>>(x, t, t & 1);
    }
    head_kernel<<<B_, 256>>>(Wlin, blin, out);
}

// round 10
// speedup vs baseline: 5.5946x; 1.5517x over previous
#include <cuda_runtime.h>
#include <cuda_fp16.h>
#include <math.h>
#include <stdint.h>

#define B_   4096
#define T_   32
#define H_   512
#define NG   2048   // 4*H
#define EMB_ 64
#define V_   256
#define O_   64

#define WSCALE 16.0f
#define INV_WSCALE 0.0625f

// ---------------- persistent scratch ----------------
__device__ float d_table[2][V_][NG];            // per-char gate preactivation (+biases), mma-column layout
__device__ __half d_w16[2][NG][H_];             // (W*16) fp16, rows = mma columns, K contiguous
__device__ __half d_hx[2][2][B_ * H_];          // [dir][pp] h (fp16-rounded)
__device__ float d_c[2][B_ * H_];               // cell state, thread-private coalesced layout

// column n (0..2047) -> torch gate row j
__device__ __forceinline__ int jmap2(int n) {
    int gate = (((n >> 3) & 1) << 1) | (n & 1);
    int u    = ((n >> 4) << 2) | ((n >> 1) & 3);
    return gate * H_ + u;
}
__device__ __forceinline__ float sig_f(float x) {
    return __fdividef(1.0f, 1.0f + __expf(-x));
}
__device__ __forceinline__ float tanh_f(float x) {
    return __fdividef(2.0f, 1.0f + __expf(-2.0f * x)) - 1.0f;
}

// ---------------- PTX helpers (plain-target safe) ----------------
__device__ __forceinline__ uint32_t smem_u32(const void* p) {
    uint32_t a;
    asm("{ .reg .u64 t; cvta.to.shared.u64 t, %1; cvt.u32.u64 %0, t; }" : "=r"(a) : "l"(p));
    return a;
}
__device__ __forceinline__ void cp16(uint32_t saddr, const void* g) {
    asm volatile("cp.async.cg.shared.global [%0], [%1], 16;" :: "r"(saddr), "l"(g));
}
#define CP_COMMIT() asm volatile("cp.async.commit_group;" ::: "memory")
#define CP_WAIT(n)  asm volatile("cp.async.wait_group %0;" :: "n"(n) : "memory")

__device__ __forceinline__ void ldsm_x4(uint32_t addr, uint32_t* r) {
    asm volatile("ldmatrix.sync.aligned.m8n8.x4.shared.b16 {%0,%1,%2,%3}, [%4];"
        : "=r"(r[0]), "=r"(r[1]), "=r"(r[2]), "=r"(r[3]) : "r"(addr));
}
__device__ __forceinline__ void mma_f16(float* c, const uint32_t* a, uint32_t b0, uint32_t b1) {
    asm volatile("mma.sync.aligned.m16n8k16.row.col.f32.f16.f16.f32 "
        "{%0,%1,%2,%3}, {%4,%5,%6,%7}, {%8,%9}, {%0,%1,%2,%3};"
        : "+f"(c[0]), "+f"(c[1]), "+f"(c[2]), "+f"(c[3])
        : "r"(a[0]), "r"(a[1]), "r"(a[2]), "r"(a[3]), "r"(b0), "r"(b1));
}

// 128B-row layout, conflict-free swizzle: 16B chunk ^= row&7
__device__ __forceinline__ uint32_t swzoff(int row, int cb) {
    uint32_t off = (uint32_t)(row * 128 + cb);
    return off ^ (uint32_t)((row & 7) << 4);
}

// ---------------- SMEM layout: CTA 128x128, K-tile 64, 3 stages ----------------
// per tile: 128 rows x 128B = 16384; per stage A, B = 32768
#define TILE_SZ  16384
#define STG_SZ   32768
#define NSTG     3
#define OFF_A(s)  ((s) * STG_SZ + 0)
#define OFF_B(s)  ((s) * STG_SZ + TILE_SZ)
#define SMEM_TOTAL (NSTG * STG_SZ)   // 98304
#define HSTG 80                      // h-staging row stride (bytes)

// ---------------- one-off precompute ----------------
__global__ void build_table(const float* __restrict__ emb,
                            const float* __restrict__ Wih1, const float* __restrict__ bih1, const float* __restrict__ bhh1,
                            const float* __restrict__ Wih2, const float* __restrict__ bih2, const float* __restrict__ bhh2) {
    int n   = blockIdx.x * 128 + threadIdx.x;
    int v   = blockIdx.y;
    int dir = blockIdx.z;
    const float* Wih = dir ? Wih2 : Wih1;
    const float* bi  = dir ? bih2 : bih1;
    const float* bh  = dir ? bhh2 : bhh1;
    int j = jmap2(n);
    float s = bi[j] + bh[j];
    const float* e = emb + v * EMB_;
    const float* w = Wih + j * EMB_;
#pragma unroll 16
    for (int k = 0; k < EMB_; k++) s += e[k] * w[k];
    d_table[dir][v][n] = s;
}

__global__ void build_wt(const float* __restrict__ Whh1, const float* __restrict__ Whh2) {
    int k   = blockIdx.x * 128 + threadIdx.x;
    int n   = blockIdx.y;
    int dir = blockIdx.z;
    const float* W = dir ? Whh2 : Whh1;
    d_w16[dir][n][k] = __float2half_rn(W[jmap2(n) * H_ + k] * WSCALE);
}

__global__ void init_state() {
    int i = blockIdx.x * 256 + threadIdx.x;
    if (i < B_ * H_) {
        __half z = __float2half_rn(0.f);
        d_hx[0][0][i] = z; d_hx[1][0][i] = z;
        d_c[0][i] = 0.f;   d_c[1][i] = 0.f;
    }
}

// ---------------- async stage: one 128x64 fp16 tile = 128 rows x 128B (256 threads) ----------------
__device__ __forceinline__ void stage_tile(uint32_t sdst,
                                           const __half* __restrict__ src,
                                           int rowbase, int k0, int tid) {
#pragma unroll
    for (int j = 0; j < 4; j++) {
        int lin = tid + j * 256;              // 0..1023
        int row = lin >> 3;                   // 0..127
        int c   = lin & 7;                    // 8 x 16B = 128B per row
        uint32_t so = (uint32_t)(row * 128 + c * 16);
        so ^= (uint32_t)((row & 7) << 4);
        cp16(sdst + so,
             (const char*)(src + (size_t)(rowbase + row) * H_ + k0) + c * 16);
    }
}

// ---------------- fused recurrent step: single-product fp16 mma ----------------
__global__ void __launch_bounds__(256, 2) lstm_step_mma(const int* __restrict__ x, int t, int pp) {
    extern __shared__ __align__(1024) char sm[];
    const int dir  = blockIdx.z;
    const int tcol = dir ? (T_ - 1 - t) : t;
    const int n0   = blockIdx.x * 128;
    const int b0   = blockIdx.y * 128;

    const __half* __restrict__ hx = d_hx[dir][pp];
    __half* __restrict__ hx_n = d_hx[dir][pp ^ 1];
    float* __restrict__ cst = d_c[dir];
    const __half* __restrict__ W = &d_w16[dir][0][0];

    const uint32_t sb = smem_u32(sm);
    const int tid  = threadIdx.x;
    const int wid  = tid >> 5;
    const int lane = tid & 31;
    const int wm   = wid >> 1;    // 0..3: 32-row band
    const int wn   = wid & 1;     // 0..1: 64-col band
    const int g    = lane >> 2;
    const int tg   = lane & 3;
    const int lrow  = lane & 15;
    const int lhalf = lane >> 4;

    // prefetch chars for the epilogue
    int chv[2][2];
#pragma unroll
    for (int i = 0; i < 2; i++) {
        const int r0 = wm * 32 + i * 16 + g;
        chv[i][0] = x[(size_t)(b0 + r0) * T_ + tcol];
        chv[i][1] = x[(size_t)(b0 + r0 + 8) * T_ + tcol];
    }

    // per-thread ldsm offsets (loop-invariant): kk in 0..3 over 128B row
    uint32_t oA[2][4], oB[4][4];
#pragma unroll
    for (int kk = 0; kk < 4; kk++) {
        const int kb = kk * 32 + lhalf * 16;
#pragma unroll
        for (int i = 0; i < 2; i++) oA[i][kk] = swzoff(wm * 32 + i * 16 + lrow, kb);
#pragma unroll
        for (int q = 0; q < 4; q++) oB[q][kk] = swzoff(wn * 64 + q * 16 + lrow, kb);
    }

    float acc[2][8][4];
#pragma unroll
    for (int i = 0; i < 2; i++)
#pragma unroll
        for (int j = 0; j < 8; j++)
#pragma unroll
            for (int r = 0; r < 4; r++) acc[i][j][r] = 0.f;

    // prologue: stage k-tiles 0,1
#pragma unroll
    for (int s = 0; s < 2; s++) {
        stage_tile(sb + OFF_A(s), hx, b0, s * 64, tid);
        stage_tile(sb + OFF_B(s), W,  n0, s * 64, tid);
        CP_COMMIT();
    }

#pragma unroll
    for (int kt = 0; kt < 8; kt++) {
        if (kt < 7) { CP_WAIT(1); } else { CP_WAIT(0); }
        __syncthreads();
        if (kt + 2 < 8) {
            const int nb = (kt + 2) % NSTG;
            const int k0 = (kt + 2) * 64;
            stage_tile(sb + OFF_A(nb), hx, b0, k0, tid);
            stage_tile(sb + OFF_B(nb), W,  n0, k0, tid);
            CP_COMMIT();
        }
        const int buf = kt % NSTG;
        const uint32_t baseA = sb + OFF_A(buf);
        const uint32_t baseB = sb + OFF_B(buf);
#pragma unroll
        for (int kk = 0; kk < 4; kk++) {
            uint32_t af[2][4], bf4[4][4];
#pragma unroll
            for (int i = 0; i < 2; i++) ldsm_x4(baseA + oA[i][kk], af[i]);
#pragma unroll
            for (int q = 0; q < 4; q++) ldsm_x4(baseB + oB[q][kk], bf4[q]);
#pragma unroll
            for (int i = 0; i < 2; i++)
#pragma unroll
                for (int q = 0; q < 4; q++)
#pragma unroll
                    for (int nb2 = 0; nb2 < 2; nb2++)
                        mma_f16(acc[i][q * 2 + nb2], af[i], bf4[q][nb2], bf4[q][nb2 + 2]);
        }
    }

    __syncthreads();   // all mma smem reads retired before epilogue staging reuse

    // ---------------- epilogue: gates + cell update, in-register ----------------
    const int cbase = (((blockIdx.y * 16 + blockIdx.x) * 256 + tid) << 4);
    float cv[16];
#pragma unroll
    for (int q = 0; q < 4; q++) *(float4*)&cv[q * 4] = *(const float4*)&cst[cbase + q * 4];

#pragma unroll
    for (int i = 0; i < 2; i++) {
        const int r0 = wm * 32 + i * 16 + g;
        const float* trow0 = &d_table[dir][chv[i][0]][n0];
        const float* trow1 = &d_table[dir][chv[i][1]][n0];
#pragma unroll
        for (int jj = 0; jj < 4; jj++) {
            const int colIF = wn * 64 + jj * 16 + 2 * tg;
            const int u_l   = (wn * 4 + jj) * 4 + tg;
#pragma unroll
            for (int half = 0; half < 2; half++) {
                const float* trow = half ? trow1 : trow0;
                const float2 tif = *(const float2*)&trow[colIF];
                const float2 tgo = *(const float2*)&trow[colIF + 8];
                float gi = fmaf(INV_WSCALE, acc[i][jj * 2 + 0][half * 2 + 0], tif.x);
                float gf = fmaf(INV_WSCALE, acc[i][jj * 2 + 0][half * 2 + 1], tif.y);
                float gg = fmaf(INV_WSCALE, acc[i][jj * 2 + 1][half * 2 + 0], tgo.x);
                float go = fmaf(INV_WSCALE, acc[i][jj * 2 + 1][half * 2 + 1], tgo.y);
                const int idx = i * 8 + jj * 2 + half;
                float c_new = sig_f(gf) * cv[idx] + sig_f(gi) * tanh_f(gg);
                cv[idx] = c_new;
                const float hv = sig_f(go) * tanh_f(c_new);
                const int rl = r0 + half * 8;
                *(__half*)(sm + rl * HSTG + u_l * 2) = __float2half_rn(hv);
            }
        }
    }
#pragma unroll
    for (int q = 0; q < 4; q++) *(float4*)&cst[cbase + q * 4] = *(const float4*)&cv[q * 4];

    __syncthreads();
    // coalesced h store: 128 rows x 32 units (64B/row)
    const int u0 = n0 >> 2;
    {
        const int row = tid >> 1;
        const int q   = tid & 1;
        uint4 v0 = *(const uint4*)(sm + row * HSTG + q * 32);
        uint4 v1 = *(const uint4*)(sm + row * HSTG + q * 32 + 16);
        char* dst = (char*)(hx_n + (size_t)(b0 + row) * H_ + u0) + q * 32;
        *(uint4*)dst = v0;
        *(uint4*)(dst + 16) = v1;
    }
}

// ---------------- classifier head + softmax ----------------
__global__ void head_kernel(const float* __restrict__ Wlin, const float* __restrict__ blin,
                            float* __restrict__ out) {
    const int b    = blockIdx.x;
    const int tid  = threadIdx.x;
    const int w    = tid >> 5;
    const int lane = tid & 31;

    __shared__ __align__(16) float hrow[1024];
    __shared__ float lg[O_];
    __shared__ float red[2];

    for (int i = tid; i < H_; i += 256) {
        hrow[i]      = __half2float(d_hx[0][0][b * H_ + i]);
        hrow[H_ + i] = __half2float(d_hx[1][0][b * H_ + i]);
    }
    __syncthreads();

    const float4* hr4 = (const float4*)hrow;
#pragma unroll
    for (int oo = 0; oo < 8; oo++) {
        const int o = w * 8 + oo;
        const float4* wl = (const float4*)(Wlin + o * 1024);
        float s = 0.f;
#pragma unroll
        for (int it = 0; it < 8; it++) {
            float4 a  = hr4[it * 32 + lane];
            float4 bw = wl[it * 32 + lane];
            s += a.x * bw.x + a.y * bw.y + a.z * bw.z + a.w * bw.w;
        }
#pragma unroll
        for (int off = 16; off; off >>= 1) s += __shfl_down_sync(0xffffffffu, s, off);
        if (lane == 0) lg[o] = s + blin[o];
    }
    __syncthreads();

    if (tid == 0) {
        float m = lg[0];
        for (int i = 1; i < O_; i++) m = fmaxf(m, lg[i]);
        red[0] = m;
    }
    __syncthreads();
    if (tid < O_) lg[tid] = expf(lg[tid] - red[0]);
    __syncthreads();
    if (tid == 0) {
        float s = 0.f;
        for (int i = 0; i < O_; i++) s += lg[i];
        red[1] = 1.0f / s;
    }
    __syncthreads();
    if (tid < O_) out[b * O_ + tid] = lg[tid] * red[1];
}

// ---------------- launch ----------------
extern "C" void kernel_launch(void* const* d_in, const int* in_sizes, int n_in,
                              void* d_out, int out_size) {
    const int*   x    = (const int*)d_in[0];
    const float* emb  = (const float*)d_in[2];
    const float* Wih1 = (const float*)d_in[3];
    const float* Whh1 = (const float*)d_in[4];
    const float* bih1 = (const float*)d_in[5];
    const float* bhh1 = (const float*)d_in[6];
    const float* Wih2 = (const float*)d_in[7];
    const float* Whh2 = (const float*)d_in[8];
    const float* bih2 = (const float*)d_in[9];
    const float* bhh2 = (const float*)d_in[10];
    const float* Wlin = (const float*)d_in[11];
    const float* blin = (const float*)d_in[12];
    float* out = (float*)d_out;

    cudaFuncSetAttribute(lstm_step_mma, cudaFuncAttributeMaxDynamicSharedMemorySize, SMEM_TOTAL);

    dim3 g1(NG / 128, V_, 2);
    build_table<<<g1, 128>>>(emb, Wih1, bih1, bhh1, Wih2, bih2, bhh2);
    dim3 g2(H_ / 128, NG, 2);
    build_wt<<<g2, 128>>>(Whh1, Whh2);
    init_state<<<(B_ * H_ + 255) / 256, 256>>>();

    dim3 gs(NG / 128, B_ / 128, 2);   // (16, 32, 2) = 1024 CTAs, 2/SM
    for (int t = 0; t < T_; t++) {
        lstm_step_mma<<<gs, 256, SMEM_TOTAL>>>(x, t, t & 1);
    }
    head_kernel<<<B_, 256>>>(Wlin, blin, out);
}